// round 2
// baseline (speedup 1.0000x reference)
#include <cuda_runtime.h>
#include <math.h>

#define A_MAX   442368
#define NKEEP   1000
#define CAND_CAP 2048

// ---------------- scratch (device globals; no allocation allowed) ----------------
__device__ unsigned            g_key[A_MAX];      // monotone-transformed score bits
__device__ int                 g_argmax[A_MAX];
__device__ unsigned            g_hist[4][256];
__device__ unsigned            g_cnt;
__device__ unsigned long long  g_cand[CAND_CAP];  // ((u64)(~key)<<32)|idx -> ascending sort
__device__ float4              g_box[NKEEP];
__device__ float               g_area[NKEEP];
__device__ float               g_cscore[NKEEP];
__device__ int                 g_ccls[NKEEP];
__device__ unsigned            g_validw[32];
__device__ unsigned            g_sup[NKEEP * 32]; // 1000 rows x 1024-bit suppression mask

// ---------------- init: zero per-launch state ----------------
__global__ void k_init() {
    int t = threadIdx.x;
    if (t < 1024) ((unsigned*)g_hist)[t] = 0;
    if (t == 0)   g_cnt = 0;
    if (t < 32)   g_validw[t] = 0;
}

// ---------------- stage 1: per-anchor max/argmax over 80 classes + hist pass 0 ----------------
__global__ void k_reduce(const float* __restrict__ cla, int A) {
    __shared__ unsigned h[8][256];
    int wid = threadIdx.x >> 5;
    for (int b = threadIdx.x & 31; b < 256; b += 32) h[wid][b] = 0;
    __syncthreads();

    int a = blockIdx.x * 256 + threadIdx.x;
    if (a < A) {
        const float4* p = reinterpret_cast<const float4*>(cla + (size_t)a * 80);
        float best = -1e30f; int bi = 0;
#pragma unroll
        for (int q = 0; q < 20; q++) {
            float4 v = p[q];
            if (v.x > best) { best = v.x; bi = 4*q;   }
            if (v.y > best) { best = v.y; bi = 4*q+1; }
            if (v.z > best) { best = v.z; bi = 4*q+2; }
            if (v.w > best) { best = v.w; bi = 4*q+3; }
        }
        unsigned bits = __float_as_uint(best);
        unsigned key  = (bits & 0x80000000u) ? ~bits : (bits | 0x80000000u);
        g_key[a]    = key;
        g_argmax[a] = bi;
        atomicAdd(&h[wid][key >> 24], 1u);
    }
    __syncthreads();
    for (int b = threadIdx.x; b < 256; b += 256) {
        unsigned s = 0;
#pragma unroll
        for (int w = 0; w < 8; w++) s += h[w][b];
        if (s) atomicAdd(&g_hist[0][b], s);
    }
}

// ---------------- block-cooperative digit selection (blockDim >= 256) ----------------
__device__ __forceinline__ void block_select(unsigned* s, const unsigned* hist,
                                             unsigned k, unsigned& d_out, unsigned& k_out) {
    int t = threadIdx.x;
    if (t < 256) s[t] = hist[t];
    __syncthreads();
    // suffix-sum: s[t] = count of digits >= t
    for (int off = 1; off < 256; off <<= 1) {
        unsigned v = 0;
        if (t < 256 && t + off < 256) v = s[t + off];
        __syncthreads();
        if (t < 256) s[t] += v;
        __syncthreads();
    }
    if (t < 256) {
        unsigned ge = s[t];
        unsigned gt = (t < 255) ? s[t + 1] : 0u;
        if (ge >= k && gt < k) { s[256] = (unsigned)t; s[257] = k - gt; }
    }
    __syncthreads();
    d_out = s[256];
    k_out = s[257];
    __syncthreads();
}

// ---------------- radix passes 1..3 (pass 0 fused into k_reduce) ----------------
__global__ void k_hist(int pass, int A) {
    __shared__ unsigned sel[258];
    __shared__ unsigned h[8][256];
    unsigned k = NKEEP, prefix = 0;
    for (int q = 0; q < pass; q++) {
        unsigned d, kn;
        block_select(sel, g_hist[q], k, d, kn);
        prefix = (prefix << 8) | d;
        k = kn;
    }
    int wid = threadIdx.x >> 5;
    for (int b = threadIdx.x & 31; b < 256; b += 32) h[wid][b] = 0;
    __syncthreads();

    int hi_shift = 32 - 8 * pass;
    int dshift   = 24 - 8 * pass;
    for (int a = blockIdx.x * blockDim.x + threadIdx.x; a < A; a += gridDim.x * blockDim.x) {
        unsigned key = g_key[a];
        if ((key >> hi_shift) == prefix)
            atomicAdd(&h[wid][(key >> dshift) & 0xFF], 1u);
    }
    __syncthreads();
    for (int b = threadIdx.x; b < 256; b += blockDim.x) {
        unsigned s = 0;
#pragma unroll
        for (int w = 0; w < 8; w++) s += h[w][b];
        if (s) atomicAdd(&g_hist[pass][b], s);
    }
}

// ---------------- compact all keys >= T (T = value of 1000th-largest key) ----------------
__global__ void k_compact(int A) {
    __shared__ unsigned sel[258];
    unsigned k = NKEEP, prefix = 0;
    for (int q = 0; q < 4; q++) {
        unsigned d, kn;
        block_select(sel, g_hist[q], k, d, kn);
        prefix = (prefix << 8) | d;
        k = kn;
    }
    unsigned T = prefix;
    for (int a = blockIdx.x * blockDim.x + threadIdx.x; a < A; a += gridDim.x * blockDim.x) {
        unsigned key = g_key[a];
        if (key >= T) {
            unsigned slot = atomicAdd(&g_cnt, 1u);
            if (slot < CAND_CAP)
                g_cand[slot] = (((unsigned long long)(~key)) << 32) | (unsigned)a;
        }
    }
}

// ---------------- sort 2048 candidates, gather + decode + clip top-1000 ----------------
__global__ void k_sortgather(const float4* __restrict__ anchors, const float4* __restrict__ reg) {
    __shared__ unsigned long long s[CAND_CAP];
    unsigned n = g_cnt; if (n > CAND_CAP) n = CAND_CAP;
    for (int i = threadIdx.x; i < CAND_CAP; i += blockDim.x)
        s[i] = (i < (int)n) ? g_cand[i] : 0xFFFFFFFFFFFFFFFFull;
    __syncthreads();

    for (unsigned kk = 2; kk <= CAND_CAP; kk <<= 1) {
        for (unsigned j = kk >> 1; j > 0; j >>= 1) {
            for (unsigned base = 0; base < CAND_CAP; base += 1024) {
                unsigned i = base + threadIdx.x;
                unsigned ixj = i ^ j;
                if (ixj > i) {
                    unsigned long long a = s[i], b = s[ixj];
                    bool up = ((i & kk) == 0);
                    if ((a > b) == up) { s[i] = b; s[ixj] = a; }
                }
            }
            __syncthreads();
        }
    }

    int i = threadIdx.x;
    if (i < NKEEP) {
        unsigned long long kk = s[i];
        unsigned idx  = (unsigned)kk;
        unsigned tkey = ~((unsigned)(kk >> 32));
        unsigned bits = (tkey & 0x80000000u) ? (tkey ^ 0x80000000u) : ~tkey;
        float sc = __uint_as_float(bits);

        float4 an = anchors[idx];
        float4 dg = reg[idx];
        float wa = an.z - an.x, ha = an.w - an.y;
        float cxa = an.x + 0.5f * wa, cya = an.y + 0.5f * ha;
        float cx = cxa + dg.x * wa, cy = cya + dg.y * ha;
        float w  = wa * expf(dg.z), hh = ha * expf(dg.w);
        float x1 = fminf(fmaxf(cx - 0.5f * w, 0.0f), 1535.0f);
        float y1 = fminf(fmaxf(cy - 0.5f * hh, 0.0f), 1535.0f);
        float x2 = fminf(fmaxf(cx + 0.5f * w, 0.0f), 1535.0f);
        float y2 = fminf(fmaxf(cy + 0.5f * hh, 0.0f), 1535.0f);

        g_box[i]    = make_float4(x1, y1, x2, y2);
        g_area[i]   = fmaxf(x2 - x1, 0.0f) * fmaxf(y2 - y1, 0.0f);
        g_cscore[i] = sc;
        g_ccls[i]   = g_argmax[idx];
        if (sc > 0.5f) atomicOr(&g_validw[i >> 5], 1u << (i & 31));
    }
}

// ---------------- suppression mask: 1024 warps, warp = (j-word, i-chunk) ----------------
__global__ void k_iou() {
    int W    = blockIdx.x * 8 + (threadIdx.x >> 5);  // 0..1023
    int lane = threadIdx.x & 31;
    int jw    = W & 31;
    int chunk = W >> 5;              // 0..31
    int i0   = chunk * 32;
    int iend = i0 + 32; if (iend > NKEEP) iend = NKEEP;
    int j = jw * 32 + lane;
    bool jv = (j < NKEEP);
    float jx1 = 0, jy1 = 0, jx2 = 0, jy2 = 0, ja = 0;
    if (jv) {
        float4 b = g_box[j];
        jx1 = b.x; jy1 = b.y; jx2 = b.z; jy2 = b.w;
        ja = g_area[j];
    }
    for (int i = i0; i < iend; i++) {
        float4 bi = g_box[i];
        float ai  = g_area[i];
        float iw = fminf(bi.z, jx2) - fmaxf(bi.x, jx1); iw = fmaxf(iw, 0.0f);
        float ih = fminf(bi.w, jy2) - fmaxf(bi.y, jy1); ih = fmaxf(ih, 0.0f);
        float inter = iw * ih;
        float uni   = ai + ja - inter;
        bool pred = jv && (inter / fmaxf(uni, 1e-8f) > 0.5f);
        unsigned m = __ballot_sync(0xFFFFFFFFu, pred);
        if (lane == 0) g_sup[i * 32 + jw] = m;
    }
}

// ---------------- sequential NMS scan (warp 0) + output write ----------------
__global__ void k_scan(float* __restrict__ out) {
    extern __shared__ unsigned ssup[];   // 32000 words = 125 KB
    __shared__ unsigned skeep[32];
    int tid = threadIdx.x;
    for (int w = tid; w < NKEEP * 32; w += blockDim.x) ssup[w] = g_sup[w];
    __syncthreads();

    if (tid < 32) {
        unsigned keep   = 0;
        unsigned validw = g_validw[tid];
        for (int i = 0; i < NKEEP; i++) {
            unsigned w = ssup[i * 32 + tid];
            unsigned any = __ballot_sync(0xFFFFFFFFu, (w & keep) != 0u);
            if ((tid == (i >> 5)) && any == 0u && ((validw >> (i & 31)) & 1u))
                keep |= 1u << (i & 31);
        }
        skeep[tid] = keep;
    }
    __syncthreads();

    if (tid < NKEEP) {
        bool kp = (skeep[tid >> 5] >> (tid & 31)) & 1u;
        out[tid]         = kp ? g_cscore[tid] : 0.0f;
        out[NKEEP + tid] = kp ? (float)g_ccls[tid] : -1.0f;
        float4 b = kp ? g_box[tid] : make_float4(0, 0, 0, 0);
        ((float4*)(out + 2 * NKEEP))[tid] = b;
    }
}

// ---------------- launch ----------------
extern "C" void kernel_launch(void* const* d_in, const int* in_sizes, int n_in,
                              void* d_out, int out_size) {
    const float*  cla     = (const float*)d_in[0];
    const float4* reg     = (const float4*)d_in[1];
    const float4* anchors = (const float4*)d_in[2];
    int A = in_sizes[0] / 80;
    float* out = (float*)d_out;

    cudaFuncSetAttribute(k_scan, cudaFuncAttributeMaxDynamicSharedMemorySize, 131072);

    k_init<<<1, 1024>>>();
    k_reduce<<<(A + 255) / 256, 256>>>(cla, A);
    k_hist<<<592, 256>>>(1, A);
    k_hist<<<592, 256>>>(2, A);
    k_hist<<<592, 256>>>(3, A);
    k_compact<<<592, 256>>>(A);
    k_sortgather<<<1, 1024>>>(anchors, reg);
    k_iou<<<128, 256>>>();
    k_scan<<<1, 1024, NKEEP * 32 * sizeof(unsigned)>>>(out);
}